// round 7
// baseline (speedup 1.0000x reference)
#include <cuda_runtime.h>

typedef unsigned long long u64;

#define B_TOTAL  32768
#define NUM_MID  6
#define PPB      16          // patches per block (8 pairs)
#define NPAIR    8
#define NTHREADS 224         // 8*25 = 200 active

// SMEM layout (floats). Plane: 5 rows x 12 floats (row = 5 pair-packed positions + pad)
#define PLANE_F   60
#define ROW_F     12
#define H_BUF     (NPAIR*25*PLANE_F)        // 12000 floats
#define W_BUF     5625                      // [25oc][25ic][9] unpadded
#define WPOST_OFF 1800                      // conv0 weights occupy [0,1800)
#define SMEM_FLOATS (H_BUF + W_BUF + 64 + 2*NPAIR*18)
#define SMEM_BYTES  (SMEM_FLOATS*4)

// ---- f32x2 helpers ----
__device__ __forceinline__ u64 f2pack(float lo, float hi) {
    u64 r; asm("mov.b64 %0,{%1,%2};" : "=l"(r) : "f"(lo), "f"(hi)); return r;
}
__device__ __forceinline__ u64 f2bcast(float v) { return f2pack(v, v); }
__device__ __forceinline__ void f2unpack(u64 a, float& lo, float& hi) {
    asm("mov.b64 {%0,%1},%2;" : "=f"(lo), "=f"(hi) : "l"(a));
}
__device__ __forceinline__ u64 f2fma(u64 a, u64 b, u64 c) {
    u64 d; asm("fma.rn.f32x2 %0,%1,%2,%3;" : "=l"(d) : "l"(a), "l"(b), "l"(c)); return d;
}

// Accumulate 3x3 SAME conv on 5x5 pair-packed planes into registers (no writes).
// Inner loops ordered so consecutive FMAs hit DISTINCT accumulators (x innermost).
template<int CIN>
__device__ __forceinline__ void conv_accum(const float* __restrict__ hin,
                                           const float* __restrict__ wrow,
                                           float bias,
                                           u64 acc[25])
{
    const u64 b2 = f2bcast(bias);
    #pragma unroll
    for (int i = 0; i < 25; i++) acc[i] = b2;

    #pragma unroll 2
    for (int ic = 0; ic < CIN; ic++) {
        const float* wp = wrow + ic * 9;   // scalar loads: no alignment requirement
        u64 ww[9];
        #pragma unroll
        for (int t = 0; t < 9; t++) ww[t] = f2bcast(wp[t]);

        const float* plane = hin + ic * PLANE_F;
        #pragma unroll
        for (int iy = 0; iy < 5; iy++) {
            const ulonglong2* rp = (const ulonglong2*)(plane + iy * ROW_F);
            ulonglong2 q0 = rp[0];
            ulonglong2 q1 = rp[1];
            u64 r[5];
            r[0] = q0.x; r[1] = q0.y; r[2] = q1.x; r[3] = q1.y;
            r[4] = *(const u64*)(plane + iy * ROW_F + 8);

            #pragma unroll
            for (int dy = 0; dy < 3; dy++) {
                const int y = iy + 1 - dy;          // output row fed by input row iy
                if (y >= 0 && y < 5) {
                    // dx OUTER, x INNER: 4-5 independent FMAs between acc reuse
                    #pragma unroll
                    for (int dx = 0; dx < 3; dx++) {
                        const u64 w2 = ww[dy*3 + dx];
                        #pragma unroll
                        for (int x = 0; x < 5; x++) {
                            const int ix = x + dx - 1;
                            if (ix >= 0 && ix < 5)
                                acc[y*5 + x] = f2fma(w2, r[ix], acc[y*5 + x]);
                        }
                    }
                }
            }
        }
    }
}

__device__ __forceinline__ void relu_store(float* __restrict__ hout, const u64 acc[25])
{
    #pragma unroll
    for (int y = 0; y < 5; y++) {
        u64 o[5];
        #pragma unroll
        for (int x = 0; x < 5; x++) {
            float lo, hi; f2unpack(acc[y*5 + x], lo, hi);
            o[x] = f2pack(fmaxf(lo, 0.0f), fmaxf(hi, 0.0f));
        }
        ulonglong2* rp = (ulonglong2*)(hout + y * ROW_F);
        rp[0] = make_ulonglong2(o[0], o[1]);
        rp[1] = make_ulonglong2(o[2], o[3]);
        *(u64*)(hout + y * ROW_F + 8) = o[4];
    }
}

__global__ __launch_bounds__(NTHREADS, 3)
void Kpcnn_49160195670356_kernel(const float* __restrict__ gin,
                                 const float* __restrict__ w0,
                                 const float* __restrict__ b0,
                                 const float* __restrict__ wmid,
                                 const float* __restrict__ bmid,
                                 const float* __restrict__ wlast,
                                 const float* __restrict__ blast,
                                 const float* __restrict__ wpost,
                                 const float* __restrict__ bpost,
                                 float* __restrict__ gout)
{
    extern __shared__ float smem[];
    float* hbuf   = smem;                // H_BUF (single buffer, in-place layers)
    float* wbuf   = hbuf + H_BUF;        // W_BUF
    float* bbuf   = wbuf + W_BUF;        // 64
    float* colorsS= bbuf + 64;           // [2 half][NPAIR][18]

    const int tid  = threadIdx.x;
    const int pair = tid / 25;
    const int oc   = tid % 25;
    const bool act = (tid < NPAIR * 25);
    const long pg  = (long)blockIdx.x * PPB;

    // ---- stage input (pair-interleaved, padded rows), conv0 weights, wpost, b0 ----
    for (int i = tid; i < PPB * 200; i += NTHREADS) {
        const int patch = i / 200;
        const int rem   = i % 200;
        const int c     = rem / 25;
        const int pos   = rem % 25;
        const int y = pos / 5, x = pos % 5;
        const float v = gin[(pg + patch) * 200 + rem];
        hbuf[((patch >> 1) * 25 + c) * PLANE_F + y * ROW_F + x * 2 + (patch & 1)] = v;
    }
    for (int i = tid; i < 25 * 8 * 9; i += NTHREADS) wbuf[i] = w0[i];
    for (int i = tid; i < 18 * 75; i += NTHREADS) wbuf[WPOST_OFF + i] = wpost[i];
    if (tid < 25) bbuf[tid] = b0[tid];
    __syncthreads();

    // ---- colors (VALID 5x5 conv on input ch 0..2): 3 indep accumulators ----
    if (act && oc < 18) {
        const float* wp = wbuf + WPOST_OFF + oc * 75;
        u64 a0 = f2bcast(__ldg(bpost + oc));
        u64 a1 = f2bcast(0.0f);
        u64 a2 = f2bcast(0.0f);
        const float* ip0 = hbuf + (pair * 25 + 0) * PLANE_F;
        const float* ip1 = hbuf + (pair * 25 + 1) * PLANE_F;
        const float* ip2 = hbuf + (pair * 25 + 2) * PLANE_F;
        #pragma unroll
        for (int k = 0; k < 25; k++) {
            const int o = (k / 5) * ROW_F + (k % 5) * 2;
            a0 = f2fma(f2bcast(wp[k]),      *(const u64*)(ip0 + o), a0);
            a1 = f2fma(f2bcast(wp[25 + k]), *(const u64*)(ip1 + o), a1);
            a2 = f2fma(f2bcast(wp[50 + k]), *(const u64*)(ip2 + o), a2);
        }
        float lo0, hi0, lo1, hi1, lo2, hi2;
        f2unpack(a0, lo0, hi0); f2unpack(a1, lo1, hi1); f2unpack(a2, lo2, hi2);
        colorsS[pair * 18 + oc] = lo0 + lo1 + lo2;
        colorsS[NPAIR * 18 + pair * 18 + oc] = hi0 + hi1 + hi2;
    }

    // ---- conv0: 8ch -> 25ch, in place ----
    {
        u64 acc[25];
        if (act)
            conv_accum<8>(hbuf + pair * 25 * PLANE_F, wbuf + oc * 72, bbuf[oc], acc);
        __syncthreads();   // all reads of input (incl. colors) complete
        if (act)
            relu_store(hbuf + (pair * 25 + oc) * PLANE_F, acc);
        __syncthreads();
    }

    // ---- mid layers, in place ----
    #pragma unroll 1
    for (int layer = 0; layer < NUM_MID; layer++) {
        const float* wg = wmid + (long)layer * W_BUF;
        for (int i = tid; i < W_BUF; i += NTHREADS) wbuf[i] = wg[i];
        if (tid < 25) bbuf[tid] = bmid[layer * 25 + tid];
        __syncthreads();
        u64 acc[25];
        if (act)
            conv_accum<25>(hbuf + pair * 25 * PLANE_F, wbuf + oc * 225, bbuf[oc], acc);
        __syncthreads();
        if (act)
            relu_store(hbuf + (pair * 25 + oc) * PLANE_F, acc);
        __syncthreads();
    }

    // ---- stage last-layer weights pre-packed pairs: [(oc*25+ic)*10 + t] u64 ----
    for (int i = tid; i < 6 * 25 * 9; i += NTHREADS) {
        const int row = i / 9, t = i % 9;
        const float v = wlast[i];
        wbuf[(row * 10 + t) * 2 + 0] = v;
        wbuf[(row * 10 + t) * 2 + 1] = v;
    }
    if (tid < 6) bbuf[tid] = blast[tid];
    __syncthreads();

    // ---- last conv (25->6) per position + softmax + einsum ----
    if (act) {
        const int j = oc;
        const int y = j / 5, x = j % 5;
        const float* hfin = hbuf + pair * 25 * PLANE_F;

        int  off[9];
        bool inb[9];
        #pragma unroll
        for (int dy = 0; dy < 3; dy++)
            #pragma unroll
            for (int dx = 0; dx < 3; dx++) {
                const int iy = y + dy - 1, ix = x + dx - 1;
                const int t = dy * 3 + dx;
                inb[t] = (iy >= 0 && iy < 5 && ix >= 0 && ix < 5);
                off[t] = inb[t] ? (iy * ROW_F + ix * 2) : 0;
            }

        u64 s[6];
        #pragma unroll
        for (int w = 0; w < 6; w++) s[w] = f2bcast(bbuf[w]);

        #pragma unroll 2
        for (int ic = 0; ic < 25; ic++) {
            const float* hp = hfin + ic * PLANE_F;
            u64 v[9];
            #pragma unroll
            for (int t = 0; t < 9; t++) v[t] = inb[t] ? *(const u64*)(hp + off[t]) : 0ULL;
            // t OUTER, w INNER: 6 independent accumulators between reuse
            #pragma unroll
            for (int t = 0; t < 9; t++) {
                #pragma unroll
                for (int w = 0; w < 6; w++) {
                    const u64 wl = ((const u64*)wbuf)[(w * 25 + ic) * 10 + t];
                    s[w] = f2fma(wl, v[t], s[w]);
                }
            }
        }

        #pragma unroll
        for (int half = 0; half < 2; half++) {
            float sv[6];
            #pragma unroll
            for (int w = 0; w < 6; w++) {
                float lo, hi; f2unpack(s[w], lo, hi);
                sv[w] = half ? hi : lo;
            }
            float m = sv[0];
            #pragma unroll
            for (int w = 1; w < 6; w++) m = fmaxf(m, sv[w]);
            float e[6], sum = 0.0f;
            #pragma unroll
            for (int w = 0; w < 6; w++) { e[w] = __expf(sv[w] - m); sum += e[w]; }
            const float inv = 1.0f / sum;

            const float* col = colorsS + half * (NPAIR * 18) + pair * 18;
            const long ob = (pg + 2 * pair + half) * 75;
            #pragma unroll
            for (int c = 0; c < 3; c++) {
                float r = 0.0f;
                #pragma unroll
                for (int w = 0; w < 6; w++) r = fmaf(col[c * 6 + w], e[w], r);
                gout[ob + c * 25 + j] = r * inv;
            }
        }
    }
}

extern "C" void kernel_launch(void* const* d_in, const int* in_sizes, int n_in,
                              void* d_out, int out_size)
{
    const float* gin   = (const float*)d_in[0];
    const float* w0    = (const float*)d_in[1];
    const float* b0    = (const float*)d_in[2];
    const float* wmid  = (const float*)d_in[3];
    const float* bmid  = (const float*)d_in[4];
    const float* wlast = (const float*)d_in[5];
    const float* blast = (const float*)d_in[6];
    const float* wpost = (const float*)d_in[7];
    const float* bpost = (const float*)d_in[8];
    float* gout = (float*)d_out;

    cudaFuncSetAttribute(Kpcnn_49160195670356_kernel,
                         cudaFuncAttributeMaxDynamicSharedMemorySize, SMEM_BYTES);

    Kpcnn_49160195670356_kernel<<<B_TOTAL / PPB, NTHREADS, SMEM_BYTES>>>(
        gin, w0, b0, wmid, bmid, wlast, blast, wpost, bpost, gout);
}

// round 8
// speedup vs baseline: 1.0136x; 1.0136x over previous
#include <cuda_runtime.h>

typedef unsigned long long u64;

#define B_TOTAL  32768
#define NUM_MID  6
#define PPB      16          // patches per block (8 pairs)
#define NPAIR    8
#define NTHREADS 224         // 8*25 = 200 active in conv phases

// SMEM layout (floats). Plane: 5 rows x 12 floats (row = 5 pair-packed positions + pad)
#define PLANE_F   60
#define ROW_F     12
#define H_BUF     (NPAIR*25*PLANE_F)        // 12000 floats
#define W_BUF     5625                      // [25oc][25ic][9] unpadded
#define WPOST_OFF 1800                      // conv0 weights occupy [0,1800)
#define SMEM_FLOATS (H_BUF + W_BUF + 64 + 2*NPAIR*18)
#define SMEM_BYTES  (SMEM_FLOATS*4)

// ---- f32x2 helpers ----
__device__ __forceinline__ u64 f2pack(float lo, float hi) {
    u64 r; asm("mov.b64 %0,{%1,%2};" : "=l"(r) : "f"(lo), "f"(hi)); return r;
}
__device__ __forceinline__ u64 f2bcast(float v) { return f2pack(v, v); }
__device__ __forceinline__ void f2unpack(u64 a, float& lo, float& hi) {
    asm("mov.b64 {%0,%1},%2;" : "=f"(lo), "=f"(hi) : "l"(a));
}
__device__ __forceinline__ u64 f2fma(u64 a, u64 b, u64 c) {
    u64 d; asm("fma.rn.f32x2 %0,%1,%2,%3;" : "=l"(d) : "l"(a), "l"(b), "l"(c)); return d;
}

// Accumulate 3x3 SAME conv on 5x5 pair-packed planes into registers (no writes).
template<int CIN>
__device__ __forceinline__ void conv_accum(const float* __restrict__ hin,
                                           const float* __restrict__ wrow,
                                           float bias,
                                           u64 acc[25])
{
    const u64 b2 = f2bcast(bias);
    #pragma unroll
    for (int i = 0; i < 25; i++) acc[i] = b2;

    #pragma unroll 2
    for (int ic = 0; ic < CIN; ic++) {
        const float* wp = wrow + ic * 9;   // scalar loads: no alignment requirement
        u64 ww[9];
        #pragma unroll
        for (int t = 0; t < 9; t++) ww[t] = f2bcast(wp[t]);

        const float* plane = hin + ic * PLANE_F;
        #pragma unroll
        for (int iy = 0; iy < 5; iy++) {
            const ulonglong2* rp = (const ulonglong2*)(plane + iy * ROW_F);
            ulonglong2 q0 = rp[0];
            ulonglong2 q1 = rp[1];
            u64 r[5];
            r[0] = q0.x; r[1] = q0.y; r[2] = q1.x; r[3] = q1.y;
            r[4] = *(const u64*)(plane + iy * ROW_F + 8);

            #pragma unroll
            for (int dy = 0; dy < 3; dy++) {
                const int y = iy + 1 - dy;          // output row fed by input row iy
                if (y >= 0 && y < 5) {
                    #pragma unroll
                    for (int dx = 0; dx < 3; dx++) {
                        const u64 w2 = ww[dy*3 + dx];
                        #pragma unroll
                        for (int x = 0; x < 5; x++) {
                            const int ix = x + dx - 1;
                            if (ix >= 0 && ix < 5)
                                acc[y*5 + x] = f2fma(w2, r[ix], acc[y*5 + x]);
                        }
                    }
                }
            }
        }
    }
}

__device__ __forceinline__ void relu_store(float* __restrict__ hout, const u64 acc[25])
{
    #pragma unroll
    for (int y = 0; y < 5; y++) {
        u64 o[5];
        #pragma unroll
        for (int x = 0; x < 5; x++) {
            float lo, hi; f2unpack(acc[y*5 + x], lo, hi);
            o[x] = f2pack(fmaxf(lo, 0.0f), fmaxf(hi, 0.0f));
        }
        ulonglong2* rp = (ulonglong2*)(hout + y * ROW_F);
        rp[0] = make_ulonglong2(o[0], o[1]);
        rp[1] = make_ulonglong2(o[2], o[3]);
        *(u64*)(hout + y * ROW_F + 8) = o[4];
    }
}

// 26 coalesced LDGs for the next layer's 5625 weights (all 224 threads help)
#define WTAIL (W_BUF - 25*NTHREADS)   // 25
__device__ __forceinline__ void load_w_regs(const float* __restrict__ wg, int tid, float wtmp[26]) {
    #pragma unroll
    for (int k = 0; k < 25; k++) wtmp[k] = wg[tid + k*NTHREADS];
    wtmp[25] = (tid < WTAIL) ? wg[tid + 25*NTHREADS] : 0.0f;
}
__device__ __forceinline__ void store_w_smem(float* __restrict__ wbuf, int tid, const float wtmp[26]) {
    #pragma unroll
    for (int k = 0; k < 25; k++) wbuf[tid + k*NTHREADS] = wtmp[k];
    if (tid < WTAIL) wbuf[tid + 25*NTHREADS] = wtmp[25];
}

__global__ __launch_bounds__(NTHREADS, 3)
void Kpcnn_49160195670356_kernel(const float* __restrict__ gin,
                                 const float* __restrict__ w0,
                                 const float* __restrict__ b0,
                                 const float* __restrict__ wmid,
                                 const float* __restrict__ bmid,
                                 const float* __restrict__ wlast,
                                 const float* __restrict__ blast,
                                 const float* __restrict__ wpost,
                                 const float* __restrict__ bpost,
                                 float* __restrict__ gout)
{
    extern __shared__ float smem[];
    float* hbuf   = smem;                // H_BUF (single buffer, in-place layers)
    float* wbuf   = hbuf + H_BUF;        // W_BUF
    float* bbuf   = wbuf + W_BUF;        // 64
    float* colorsS= bbuf + 64;           // [2 half][NPAIR][18]

    const int tid  = threadIdx.x;
    const int pair = tid / 25;
    const int oc   = tid % 25;
    const bool act = (tid < NPAIR * 25);
    const long pg  = (long)blockIdx.x * PPB;

    // ---- stage input (pair-interleaved, padded rows), conv0 weights, wpost, b0 ----
    for (int i = tid; i < PPB * 200; i += NTHREADS) {
        const int patch = i / 200;
        const int rem   = i % 200;
        const int c     = rem / 25;
        const int pos   = rem % 25;
        const int y = pos / 5, x = pos % 5;
        const float v = gin[(pg + patch) * 200 + rem];
        hbuf[((patch >> 1) * 25 + c) * PLANE_F + y * ROW_F + x * 2 + (patch & 1)] = v;
    }
    for (int i = tid; i < 25 * 8 * 9; i += NTHREADS) wbuf[i] = w0[i];
    for (int i = tid; i < 18 * 75; i += NTHREADS) wbuf[WPOST_OFF + i] = wpost[i];
    if (tid < 25) bbuf[tid] = b0[tid];
    __syncthreads();

    // ---- colors (VALID 5x5 conv on input ch 0..2): 3 indep accumulators ----
    if (act && oc < 18) {
        const float* wp = wbuf + WPOST_OFF + oc * 75;
        u64 a0 = f2bcast(__ldg(bpost + oc));
        u64 a1 = f2bcast(0.0f);
        u64 a2 = f2bcast(0.0f);
        const float* ip0 = hbuf + (pair * 25 + 0) * PLANE_F;
        const float* ip1 = hbuf + (pair * 25 + 1) * PLANE_F;
        const float* ip2 = hbuf + (pair * 25 + 2) * PLANE_F;
        #pragma unroll
        for (int k = 0; k < 25; k++) {
            const int o = (k / 5) * ROW_F + (k % 5) * 2;
            a0 = f2fma(f2bcast(wp[k]),      *(const u64*)(ip0 + o), a0);
            a1 = f2fma(f2bcast(wp[25 + k]), *(const u64*)(ip1 + o), a1);
            a2 = f2fma(f2bcast(wp[50 + k]), *(const u64*)(ip2 + o), a2);
        }
        float lo0, hi0, lo1, hi1, lo2, hi2;
        f2unpack(a0, lo0, hi0); f2unpack(a1, lo1, hi1); f2unpack(a2, lo2, hi2);
        colorsS[pair * 18 + oc] = lo0 + lo1 + lo2;
        colorsS[NPAIR * 18 + pair * 18 + oc] = hi0 + hi1 + hi2;
    }

    // ---- conv0 accum (reads input + w0 from wbuf) ----
    {
        u64 acc[25];
        if (act)
            conv_accum<8>(hbuf + pair * 25 * PLANE_F, wbuf + oc * 72, bbuf[oc], acc);
        __syncthreads();   // all reads of input (incl. colors) + wbuf complete

        // phase A0: LDG wmid[0] -> regs, store conv0 acts, STS weights, bias
        float wtmp[26];
        load_w_regs(wmid, tid, wtmp);
        if (act) relu_store(hbuf + (pair * 25 + oc) * PLANE_F, acc);
        store_w_smem(wbuf, tid, wtmp);
        if (tid < 25) bbuf[tid] = bmid[tid];
        __syncthreads();
    }

    // ---- mid layers: accum; bar; {store + prefetch next weights}; bar ----
    #pragma unroll 1
    for (int layer = 0; layer < NUM_MID; layer++) {
        u64 acc[25];
        if (act)
            conv_accum<25>(hbuf + pair * 25 * PLANE_F, wbuf + oc * 225, bbuf[oc], acc);
        __syncthreads();   // accum reads of hbuf + wbuf complete

        if (layer < NUM_MID - 1) {
            float wtmp[26];
            load_w_regs(wmid + (long)(layer + 1) * W_BUF, tid, wtmp);
            if (act) relu_store(hbuf + (pair * 25 + oc) * PLANE_F, acc);
            store_w_smem(wbuf, tid, wtmp);
            if (tid < 25) bbuf[tid] = bmid[(layer + 1) * 25 + tid];
        } else {
            // last store phase: store acts + stage wlast pre-packed pairs + blast
            if (act) relu_store(hbuf + (pair * 25 + oc) * PLANE_F, acc);
            for (int i = tid; i < 6 * 25 * 9; i += NTHREADS) {
                const int row = i / 9, t = i % 9;
                const float v = wlast[i];
                wbuf[(row * 10 + t) * 2 + 0] = v;
                wbuf[(row * 10 + t) * 2 + 1] = v;
            }
            if (tid < 6) bbuf[tid] = blast[tid];
        }
        __syncthreads();
    }

    // ---- last conv (25->6) per position + softmax + einsum ----
    if (act) {
        const int j = oc;
        const int y = j / 5, x = j % 5;
        const float* hfin = hbuf + pair * 25 * PLANE_F;

        int  off[9];
        bool inb[9];
        #pragma unroll
        for (int dy = 0; dy < 3; dy++)
            #pragma unroll
            for (int dx = 0; dx < 3; dx++) {
                const int iy = y + dy - 1, ix = x + dx - 1;
                const int t = dy * 3 + dx;
                inb[t] = (iy >= 0 && iy < 5 && ix >= 0 && ix < 5);
                off[t] = inb[t] ? (iy * ROW_F + ix * 2) : 0;
            }

        u64 s[6];
        #pragma unroll
        for (int w = 0; w < 6; w++) s[w] = f2bcast(bbuf[w]);

        #pragma unroll 2
        for (int ic = 0; ic < 25; ic++) {
            const float* hp = hfin + ic * PLANE_F;
            u64 v[9];
            #pragma unroll
            for (int t = 0; t < 9; t++) v[t] = inb[t] ? *(const u64*)(hp + off[t]) : 0ULL;
            #pragma unroll
            for (int t = 0; t < 9; t++) {
                #pragma unroll
                for (int w = 0; w < 6; w++) {
                    const u64 wl = ((const u64*)wbuf)[(w * 25 + ic) * 10 + t];
                    s[w] = f2fma(wl, v[t], s[w]);
                }
            }
        }

        #pragma unroll
        for (int half = 0; half < 2; half++) {
            float sv[6];
            #pragma unroll
            for (int w = 0; w < 6; w++) {
                float lo, hi; f2unpack(s[w], lo, hi);
                sv[w] = half ? hi : lo;
            }
            float m = sv[0];
            #pragma unroll
            for (int w = 1; w < 6; w++) m = fmaxf(m, sv[w]);
            float e[6], sum = 0.0f;
            #pragma unroll
            for (int w = 0; w < 6; w++) { e[w] = __expf(sv[w] - m); sum += e[w]; }
            const float inv = 1.0f / sum;

            const float* col = colorsS + half * (NPAIR * 18) + pair * 18;
            const long ob = (pg + 2 * pair + half) * 75;
            #pragma unroll
            for (int c = 0; c < 3; c++) {
                float r = 0.0f;
                #pragma unroll
                for (int w = 0; w < 6; w++) r = fmaf(col[c * 6 + w], e[w], r);
                gout[ob + c * 25 + j] = r * inv;
            }
        }
    }
}

extern "C" void kernel_launch(void* const* d_in, const int* in_sizes, int n_in,
                              void* d_out, int out_size)
{
    const float* gin   = (const float*)d_in[0];
    const float* w0    = (const float*)d_in[1];
    const float* b0    = (const float*)d_in[2];
    const float* wmid  = (const float*)d_in[3];
    const float* bmid  = (const float*)d_in[4];
    const float* wlast = (const float*)d_in[5];
    const float* blast = (const float*)d_in[6];
    const float* wpost = (const float*)d_in[7];
    const float* bpost = (const float*)d_in[8];
    float* gout = (float*)d_out;

    cudaFuncSetAttribute(Kpcnn_49160195670356_kernel,
                         cudaFuncAttributeMaxDynamicSharedMemorySize, SMEM_BYTES);

    Kpcnn_49160195670356_kernel<<<B_TOTAL / PPB, NTHREADS, SMEM_BYTES>>>(
        gin, w0, b0, wmid, bmid, wlast, blast, wpost, bpost, gout);
}